// round 1
// baseline (speedup 1.0000x reference)
#include <cuda_runtime.h>

#define DEVFN __device__ __forceinline__

// ---------------------------------------------------------------------------
// Packed f32x2 helpers (Blackwell FFMA2: 2x fp32 throughput vs scalar FFMA)
// ---------------------------------------------------------------------------
DEVFN unsigned long long pack2(float lo, float hi) {
    unsigned long long r;
    asm("mov.b64 %0, {%1, %2};" : "=l"(r) : "f"(lo), "f"(hi));
    return r;
}
DEVFN unsigned long long fma2(unsigned long long a, unsigned long long b,
                              unsigned long long c) {
    unsigned long long d;
    asm("fma.rn.f32x2 %0, %1, %2, %3;" : "=l"(d) : "l"(a), "l"(b), "l"(c));
    return d;
}
DEVFN unsigned long long mul2(unsigned long long a, unsigned long long b) {
    unsigned long long d;
    asm("mul.rn.f32x2 %0, %1, %2;" : "=l"(d) : "l"(a), "l"(b));
    return d;
}
DEVFN float2 unpk2(unsigned long long v) {
    float2 f;
    asm("mov.b64 {%0, %1}, %2;" : "=f"(f.x), "=f"(f.y) : "l"(v));
    return f;
}

// ---------------------------------------------------------------------------
// Scratch (B*c2*H*W = 2*96*64*64 = 786432 floats each). Flat layout of these
// arrays is EXACTLY the reference's raw BCHW reshape: row n, col j of the
// [8192,96] matrix is element n*96+j.
// ---------------------------------------------------------------------------
__device__ float g_q[786432];
__device__ float g_k[786432];
__device__ float g_v[786432];
__device__ float g_o[786432];

// ---------------------------------------------------------------------------
// 1x1 conv as GEMM: C[b][m][p] = sum_k A[m][k] * B[b][k][p] (+bias, +resid)
// A: [Mtot][KDIM] row-major weights. B: [2][KDIM][4096]. C: [2][Mtot][4096].
// Tile: BM=96, BN=128, BK=16, 256 threads, 6x8 register tile per thread,
// all FMAs as f32x2 (pack along the N dimension).
// grid: (32, 2, Mtot/96)
// ---------------------------------------------------------------------------
template <int KDIM, bool RESID>
__global__ __launch_bounds__(256) void conv1x1_kernel(
    const float* __restrict__ A, const float* __restrict__ bias,
    const float* __restrict__ B, const float* __restrict__ R,
    float* __restrict__ C, int Mtot) {
    __shared__ float AsT[16][98];   // [k][r], padded stride 98
    __shared__ float Bs[16][128];   // [k][n]

    const int tid = threadIdx.x;
    const int tx = tid & 15;
    const int ty = tid >> 4;
    const int mo = blockIdx.z * 96;
    const int b = blockIdx.y;
    const int n0 = blockIdx.x * 128;
    const float* Ab = A + (size_t)mo * KDIM;
    const float* Bb = B + (size_t)b * KDIM * 4096 + n0;

    const int r0 = ty * 6;
    const int c0 = tx * 8;

    unsigned long long acc[6][4];
#pragma unroll
    for (int r = 0; r < 6; ++r)
#pragma unroll
        for (int j = 0; j < 4; ++j) acc[r][j] = 0ULL;

    for (int kc = 0; kc < KDIM; kc += 16) {
        __syncthreads();
        // A tile: [96][16] -> AsT[k][r]; global reads coalesced along k.
        for (int i = tid; i < 96 * 16; i += 256) {
            int k = i & 15, r = i >> 4;
            AsT[k][r] = Ab[r * KDIM + kc + k];
        }
        // B tile: [16][128]; coalesced along n.
        for (int i = tid; i < 16 * 128; i += 256) {
            int n = i & 127, k = i >> 7;
            Bs[k][n] = Bb[(size_t)(kc + k) * 4096 + n];
        }
        __syncthreads();
#pragma unroll
        for (int k = 0; k < 16; ++k) {
            float2 a01 = *(const float2*)&AsT[k][r0];
            float2 a23 = *(const float2*)&AsT[k][r0 + 2];
            float2 a45 = *(const float2*)&AsT[k][r0 + 4];
            ulonglong2 bv0 = *(const ulonglong2*)&Bs[k][c0];
            ulonglong2 bv1 = *(const ulonglong2*)&Bs[k][c0 + 4];
            float av[6] = {a01.x, a01.y, a23.x, a23.y, a45.x, a45.y};
#pragma unroll
            for (int r = 0; r < 6; ++r) {
                unsigned long long ap = pack2(av[r], av[r]);
                acc[r][0] = fma2(ap, bv0.x, acc[r][0]);
                acc[r][1] = fma2(ap, bv0.y, acc[r][1]);
                acc[r][2] = fma2(ap, bv1.x, acc[r][2]);
                acc[r][3] = fma2(ap, bv1.y, acc[r][3]);
            }
        }
    }
    // Epilogue: bias (+ residual), vectorized stores.
#pragma unroll
    for (int r = 0; r < 6; ++r) {
        int m = mo + r0 + r;
        float bv = bias[m];
        size_t base = ((size_t)b * Mtot + m) * 4096 + n0 + c0;
        float o[8];
#pragma unroll
        for (int j = 0; j < 4; ++j) {
            float2 t = unpk2(acc[r][j]);
            o[2 * j] = t.x + bv;
            o[2 * j + 1] = t.y + bv;
        }
        if (RESID) {
            float4 rA = *(const float4*)&R[base];
            float4 rB = *(const float4*)&R[base + 4];
            o[0] += rA.x; o[1] += rA.y; o[2] += rA.z; o[3] += rA.w;
            o[4] += rB.x; o[5] += rB.y; o[6] += rB.z; o[7] += rB.w;
        }
        *(float4*)&C[base] = make_float4(o[0], o[1], o[2], o[3]);
        *(float4*)&C[base + 4] = make_float4(o[4], o[5], o[6], o[7]);
    }
}

// ---------------------------------------------------------------------------
// Flash attention over the flat [8192, 96] matrices.
// Block: 64 query rows. Tiles of 64 keys. 256 threads.
//   S phase: 16x16 thread grid, 4x4 S tile per thread, f32x2 packed FMAs,
//            operands from Q^T / K^T in smem via LDS.128.
//   Softmax: shuffle reductions across the 16 tx lanes owning one row.
//   PV phase: 32x8 thread grid, 2 rows x 12 cols of O per thread.
// Dynamic smem: 94208 B.
// ---------------------------------------------------------------------------
#define ATTN_SMEM_FLOATS (96 * 68 + 96 * 68 + 64 * 96 + 64 * 65 + 192)
#define ATTN_SMEM_BYTES (ATTN_SMEM_FLOATS * 4)

__global__ __launch_bounds__(256, 1) void attn_kernel() {
    extern __shared__ float sm[];
    float* QsT = sm;                    // [96][68]
    float* KsT = sm + 96 * 68;          // [96][68]
    float* Vs = KsT + 96 * 68;          // [64][96]
    float* Ss = Vs + 64 * 96;           // [64][65]
    float* m_s = Ss + 64 * 65;          // [64]
    float* l_s = m_s + 64;              // [64]
    float* al_s = m_s + 128;            // [64]

    const int tid = threadIdx.x;
    const int tx = tid & 15;
    const int ty = tid >> 4;
    const int row0g = blockIdx.x * 64;

    // Load Q tile transposed: QsT[d][r] = Q[row0g+r][d]
    for (int i = tid; i < 64 * 96; i += 256) {
        int r = i / 96, d = i - r * 96;
        QsT[d * 68 + r] = g_q[(size_t)(row0g + r) * 96 + d];
    }
    if (tid < 64) {
        m_s[tid] = __int_as_float(0xff800000);  // -inf
        l_s[tid] = 0.0f;
    }

    const int r0 = ty * 4;          // S-phase rows
    const int c0 = tx * 4;          // S-phase cols
    const int pr0 = (tid >> 3) * 2; // PV rows
    const int pc0 = (tid & 7) * 12; // PV cols

    unsigned long long acc[12];
#pragma unroll
    for (int j = 0; j < 12; ++j) acc[j] = 0ULL;

    for (int kt = 0; kt < 128; ++kt) {
        __syncthreads();  // previous PV done reading Vs/Ss
        const int k0 = kt * 64;
        for (int i = tid; i < 64 * 96; i += 256) {
            int r = i / 96, d = i - r * 96;
            KsT[d * 68 + r] = g_k[(size_t)(k0 + r) * 96 + d];
        }
        for (int i = tid; i < (64 * 96) / 4; i += 256) {
            ((float4*)Vs)[i] = ((const float4*)(g_v + (size_t)k0 * 96))[i];
        }
        __syncthreads();

        // ---- S = Q K^T (4x4 per thread, packed) ----
        unsigned long long s2[4][2];
#pragma unroll
        for (int r = 0; r < 4; ++r) { s2[r][0] = 0ULL; s2[r][1] = 0ULL; }
#pragma unroll 8
        for (int d = 0; d < 96; ++d) {
            float4 q = *(const float4*)&QsT[d * 68 + r0];
            ulonglong2 kk = *(const ulonglong2*)&KsT[d * 68 + c0];
            unsigned long long q0 = pack2(q.x, q.x);
            unsigned long long q1 = pack2(q.y, q.y);
            unsigned long long q2 = pack2(q.z, q.z);
            unsigned long long q3 = pack2(q.w, q.w);
            s2[0][0] = fma2(q0, kk.x, s2[0][0]);
            s2[0][1] = fma2(q0, kk.y, s2[0][1]);
            s2[1][0] = fma2(q1, kk.x, s2[1][0]);
            s2[1][1] = fma2(q1, kk.y, s2[1][1]);
            s2[2][0] = fma2(q2, kk.x, s2[2][0]);
            s2[2][1] = fma2(q2, kk.y, s2[2][1]);
            s2[3][0] = fma2(q3, kk.x, s2[3][0]);
            s2[3][1] = fma2(q3, kk.y, s2[3][1]);
        }
        float s[4][4];
#pragma unroll
        for (int r = 0; r < 4; ++r) {
            float2 t0 = unpk2(s2[r][0]);
            float2 t1 = unpk2(s2[r][1]);
            s[r][0] = t0.x; s[r][1] = t0.y; s[r][2] = t1.x; s[r][3] = t1.y;
        }

        // ---- online softmax ----
#pragma unroll
        for (int r = 0; r < 4; ++r) {
            int row = r0 + r;
            float rm = fmaxf(fmaxf(s[r][0], s[r][1]), fmaxf(s[r][2], s[r][3]));
            rm = fmaxf(rm, __shfl_xor_sync(0xffffffffu, rm, 8));
            rm = fmaxf(rm, __shfl_xor_sync(0xffffffffu, rm, 4));
            rm = fmaxf(rm, __shfl_xor_sync(0xffffffffu, rm, 2));
            rm = fmaxf(rm, __shfl_xor_sync(0xffffffffu, rm, 1));
            float mo = m_s[row];
            float mn = fmaxf(mo, rm);
            float al = __expf(mo - mn);
            float ps = 0.0f;
#pragma unroll
            for (int c = 0; c < 4; ++c) {
                float p = __expf(s[r][c] - mn);
                Ss[row * 65 + c0 + c] = p;
                ps += p;
            }
            ps += __shfl_xor_sync(0xffffffffu, ps, 8);
            ps += __shfl_xor_sync(0xffffffffu, ps, 4);
            ps += __shfl_xor_sync(0xffffffffu, ps, 2);
            ps += __shfl_xor_sync(0xffffffffu, ps, 1);
            if (tx == 0) {
                m_s[row] = mn;
                al_s[row] = al;
                l_s[row] = l_s[row] * al + ps;
            }
        }
        __syncthreads();  // P + alpha visible

        // ---- O = alpha*O + P V (2x12 per thread, packed) ----
        {
            float a0f = al_s[pr0];
            float a1f = al_s[pr0 + 1];
            unsigned long long aa0 = pack2(a0f, a0f);
            unsigned long long aa1 = pack2(a1f, a1f);
#pragma unroll
            for (int j = 0; j < 6; ++j) {
                acc[j] = mul2(acc[j], aa0);
                acc[6 + j] = mul2(acc[6 + j], aa1);
            }
#pragma unroll 4
            for (int k = 0; k < 64; ++k) {
                float p0 = Ss[pr0 * 65 + k];
                float p1 = Ss[(pr0 + 1) * 65 + k];
                unsigned long long pp0 = pack2(p0, p0);
                unsigned long long pp1 = pack2(p1, p1);
                const ulonglong2* vp = (const ulonglong2*)&Vs[k * 96 + pc0];
                ulonglong2 v0 = vp[0];
                ulonglong2 v1 = vp[1];
                ulonglong2 v2 = vp[2];
                acc[0] = fma2(pp0, v0.x, acc[0]);
                acc[1] = fma2(pp0, v0.y, acc[1]);
                acc[2] = fma2(pp0, v1.x, acc[2]);
                acc[3] = fma2(pp0, v1.y, acc[3]);
                acc[4] = fma2(pp0, v2.x, acc[4]);
                acc[5] = fma2(pp0, v2.y, acc[5]);
                acc[6] = fma2(pp1, v0.x, acc[6]);
                acc[7] = fma2(pp1, v0.y, acc[7]);
                acc[8] = fma2(pp1, v1.x, acc[8]);
                acc[9] = fma2(pp1, v1.y, acc[9]);
                acc[10] = fma2(pp1, v2.x, acc[10]);
                acc[11] = fma2(pp1, v2.y, acc[11]);
            }
        }
    }

    // ---- finalize: O /= l ----
    float inv0 = 1.0f / l_s[pr0];
    float inv1 = 1.0f / l_s[pr0 + 1];
    float4* o0 = (float4*)&g_o[(size_t)(row0g + pr0) * 96 + pc0];
    float4* o1 = (float4*)&g_o[(size_t)(row0g + pr0 + 1) * 96 + pc0];
#pragma unroll
    for (int j = 0; j < 3; ++j) {
        float2 p0 = unpk2(acc[2 * j]);
        float2 p1 = unpk2(acc[2 * j + 1]);
        o0[j] = make_float4(p0.x * inv0, p0.y * inv0, p1.x * inv0, p1.y * inv0);
        float2 q0 = unpk2(acc[6 + 2 * j]);
        float2 q1 = unpk2(acc[6 + 2 * j + 1]);
        o1[j] = make_float4(q0.x * inv1, q0.y * inv1, q1.x * inv1, q1.y * inv1);
    }
}

// ---------------------------------------------------------------------------
// Launch: qkv (3 GEMMs) -> flash attention -> final conv + bias + residual
// ---------------------------------------------------------------------------
extern "C" void kernel_launch(void* const* d_in, const int* in_sizes, int n_in,
                              void* d_out, int out_size) {
    (void)in_sizes; (void)n_in; (void)out_size;
    const float* x = (const float*)d_in[0];
    const float* w1 = (const float*)d_in[1];
    const float* b1 = (const float*)d_in[2];
    const float* w2 = (const float*)d_in[3];
    const float* b2 = (const float*)d_in[4];
    const float* w3 = (const float*)d_in[5];
    const float* b3 = (const float*)d_in[6];
    const float* wl = (const float*)d_in[7];
    const float* bl = (const float*)d_in[8];
    float* out = (float*)d_out;

    void *qp, *kp, *vp, *op;
    cudaGetSymbolAddress(&qp, g_q);
    cudaGetSymbolAddress(&kp, g_k);
    cudaGetSymbolAddress(&vp, g_v);
    cudaGetSymbolAddress(&op, g_o);

    cudaFuncSetAttribute(attn_kernel, cudaFuncAttributeMaxDynamicSharedMemorySize,
                         ATTN_SMEM_BYTES);

    dim3 gqkv(32, 2, 1);
    conv1x1_kernel<192, false><<<gqkv, 256>>>(w1, b1, x, nullptr, (float*)qp, 96);
    conv1x1_kernel<192, false><<<gqkv, 256>>>(w2, b2, x, nullptr, (float*)kp, 96);
    conv1x1_kernel<192, false><<<gqkv, 256>>>(w3, b3, x, nullptr, (float*)vp, 96);

    attn_kernel<<<128, 256, ATTN_SMEM_BYTES>>>();

    dim3 gfin(32, 2, 2);
    conv1x1_kernel<96, true><<<gfin, 256>>>(wl, bl, (const float*)op, x, out, 192);
}

// round 2
// speedup vs baseline: 1.0012x; 1.0012x over previous
#include <cuda_runtime.h>

#define DEVFN __device__ __forceinline__

// ---------------------------------------------------------------------------
// Packed f32x2 helpers (Blackwell FFMA2: 2x fp32 throughput vs scalar FFMA)
// ---------------------------------------------------------------------------
DEVFN unsigned long long pack2(float lo, float hi) {
    unsigned long long r;
    asm("mov.b64 %0, {%1, %2};" : "=l"(r) : "f"(lo), "f"(hi));
    return r;
}
DEVFN unsigned long long fma2(unsigned long long a, unsigned long long b,
                              unsigned long long c) {
    unsigned long long d;
    asm("fma.rn.f32x2 %0, %1, %2, %3;" : "=l"(d) : "l"(a), "l"(b), "l"(c));
    return d;
}
DEVFN unsigned long long mul2(unsigned long long a, unsigned long long b) {
    unsigned long long d;
    asm("mul.rn.f32x2 %0, %1, %2;" : "=l"(d) : "l"(a), "l"(b));
    return d;
}
DEVFN float2 unpk2(unsigned long long v) {
    float2 f;
    asm("mov.b64 {%0, %1}, %2;" : "=f"(f.x), "=f"(f.y) : "l"(v));
    return f;
}

// ---------------------------------------------------------------------------
// Scratch (B*c2*H*W = 2*96*64*64 = 786432 floats each). Flat layout of these
// arrays is EXACTLY the reference's raw BCHW reshape: row n, col j of the
// [8192,96] matrix is element n*96+j.
// ---------------------------------------------------------------------------
__device__ float g_q[786432];
__device__ float g_k[786432];
__device__ float g_v[786432];
__device__ float g_o[786432];

// ---------------------------------------------------------------------------
// 1x1 conv as GEMM: C[b][m][p] = sum_k A[m][k] * B[b][k][p] (+bias, +resid)
// A: [Mtot][KDIM] row-major weights. B: [2][KDIM][4096]. C: [2][Mtot][4096].
// Tile: BM=96, BN=128, BK=16, 256 threads, 6x8 register tile per thread,
// all FMAs as f32x2 (pack along the N dimension).
// grid: (32, 2, Mtot/96)
// ---------------------------------------------------------------------------
template <int KDIM, bool RESID>
__global__ __launch_bounds__(256) void conv1x1_kernel(
    const float* __restrict__ A, const float* __restrict__ bias,
    const float* __restrict__ B, const float* __restrict__ R,
    float* __restrict__ C, int Mtot) {
    __shared__ float AsT[16][98];   // [k][r], padded stride 98
    __shared__ float Bs[16][128];   // [k][n]

    const int tid = threadIdx.x;
    const int tx = tid & 15;
    const int ty = tid >> 4;
    const int mo = blockIdx.z * 96;
    const int b = blockIdx.y;
    const int n0 = blockIdx.x * 128;
    const float* Ab = A + (size_t)mo * KDIM;
    const float* Bb = B + (size_t)b * KDIM * 4096 + n0;

    const int r0 = ty * 6;
    const int c0 = tx * 8;

    unsigned long long acc[6][4];
#pragma unroll
    for (int r = 0; r < 6; ++r)
#pragma unroll
        for (int j = 0; j < 4; ++j) acc[r][j] = 0ULL;

    for (int kc = 0; kc < KDIM; kc += 16) {
        __syncthreads();
        // A tile: [96][16] -> AsT[k][r]; global reads coalesced along k.
        for (int i = tid; i < 96 * 16; i += 256) {
            int k = i & 15, r = i >> 4;
            AsT[k][r] = Ab[r * KDIM + kc + k];
        }
        // B tile: [16][128]; coalesced along n.
        for (int i = tid; i < 16 * 128; i += 256) {
            int n = i & 127, k = i >> 7;
            Bs[k][n] = Bb[(size_t)(kc + k) * 4096 + n];
        }
        __syncthreads();
#pragma unroll
        for (int k = 0; k < 16; ++k) {
            float2 a01 = *(const float2*)&AsT[k][r0];
            float2 a23 = *(const float2*)&AsT[k][r0 + 2];
            float2 a45 = *(const float2*)&AsT[k][r0 + 4];
            ulonglong2 bv0 = *(const ulonglong2*)&Bs[k][c0];
            ulonglong2 bv1 = *(const ulonglong2*)&Bs[k][c0 + 4];
            float av[6] = {a01.x, a01.y, a23.x, a23.y, a45.x, a45.y};
#pragma unroll
            for (int r = 0; r < 6; ++r) {
                unsigned long long ap = pack2(av[r], av[r]);
                acc[r][0] = fma2(ap, bv0.x, acc[r][0]);
                acc[r][1] = fma2(ap, bv0.y, acc[r][1]);
                acc[r][2] = fma2(ap, bv1.x, acc[r][2]);
                acc[r][3] = fma2(ap, bv1.y, acc[r][3]);
            }
        }
    }
    // Epilogue: bias (+ residual), vectorized stores.
#pragma unroll
    for (int r = 0; r < 6; ++r) {
        int m = mo + r0 + r;
        float bv = bias[m];
        size_t base = ((size_t)b * Mtot + m) * 4096 + n0 + c0;
        float o[8];
#pragma unroll
        for (int j = 0; j < 4; ++j) {
            float2 t = unpk2(acc[r][j]);
            o[2 * j] = t.x + bv;
            o[2 * j + 1] = t.y + bv;
        }
        if (RESID) {
            float4 rA = *(const float4*)&R[base];
            float4 rB = *(const float4*)&R[base + 4];
            o[0] += rA.x; o[1] += rA.y; o[2] += rA.z; o[3] += rA.w;
            o[4] += rB.x; o[5] += rB.y; o[6] += rB.z; o[7] += rB.w;
        }
        *(float4*)&C[base] = make_float4(o[0], o[1], o[2], o[3]);
        *(float4*)&C[base + 4] = make_float4(o[4], o[5], o[6], o[7]);
    }
}

// ---------------------------------------------------------------------------
// Flash attention over the flat [8192, 96] matrices.
// Block: 64 query rows. Tiles of 64 keys. 256 threads.
//   S phase: 16x16 thread grid, 4x4 S tile per thread, f32x2 packed FMAs,
//            operands from Q^T / K^T in smem via LDS.128.
//   Softmax: shuffle reductions across the 16 tx lanes owning one row.
//   PV phase: 32x8 thread grid, 2 rows x 12 cols of O per thread.
// Dynamic smem: 94208 B.
// ---------------------------------------------------------------------------
#define ATTN_SMEM_FLOATS (96 * 68 + 96 * 68 + 64 * 96 + 64 * 65 + 192)
#define ATTN_SMEM_BYTES (ATTN_SMEM_FLOATS * 4)

__global__ __launch_bounds__(256, 1) void attn_kernel() {
    extern __shared__ float sm[];
    float* QsT = sm;                    // [96][68]
    float* KsT = sm + 96 * 68;          // [96][68]
    float* Vs = KsT + 96 * 68;          // [64][96]
    float* Ss = Vs + 64 * 96;           // [64][65]
    float* m_s = Ss + 64 * 65;          // [64]
    float* l_s = m_s + 64;              // [64]
    float* al_s = m_s + 128;            // [64]

    const int tid = threadIdx.x;
    const int tx = tid & 15;
    const int ty = tid >> 4;
    const int row0g = blockIdx.x * 64;

    // Load Q tile transposed: QsT[d][r] = Q[row0g+r][d]
    for (int i = tid; i < 64 * 96; i += 256) {
        int r = i / 96, d = i - r * 96;
        QsT[d * 68 + r] = g_q[(size_t)(row0g + r) * 96 + d];
    }
    if (tid < 64) {
        m_s[tid] = __int_as_float(0xff800000);  // -inf
        l_s[tid] = 0.0f;
    }

    const int r0 = ty * 4;          // S-phase rows
    const int c0 = tx * 4;          // S-phase cols
    const int pr0 = (tid >> 3) * 2; // PV rows
    const int pc0 = (tid & 7) * 12; // PV cols

    unsigned long long acc[12];
#pragma unroll
    for (int j = 0; j < 12; ++j) acc[j] = 0ULL;

    for (int kt = 0; kt < 128; ++kt) {
        __syncthreads();  // previous PV done reading Vs/Ss
        const int k0 = kt * 64;
        for (int i = tid; i < 64 * 96; i += 256) {
            int r = i / 96, d = i - r * 96;
            KsT[d * 68 + r] = g_k[(size_t)(k0 + r) * 96 + d];
        }
        for (int i = tid; i < (64 * 96) / 4; i += 256) {
            ((float4*)Vs)[i] = ((const float4*)(g_v + (size_t)k0 * 96))[i];
        }
        __syncthreads();

        // ---- S = Q K^T (4x4 per thread, packed) ----
        unsigned long long s2[4][2];
#pragma unroll
        for (int r = 0; r < 4; ++r) { s2[r][0] = 0ULL; s2[r][1] = 0ULL; }
#pragma unroll 8
        for (int d = 0; d < 96; ++d) {
            float4 q = *(const float4*)&QsT[d * 68 + r0];
            ulonglong2 kk = *(const ulonglong2*)&KsT[d * 68 + c0];
            unsigned long long q0 = pack2(q.x, q.x);
            unsigned long long q1 = pack2(q.y, q.y);
            unsigned long long q2 = pack2(q.z, q.z);
            unsigned long long q3 = pack2(q.w, q.w);
            s2[0][0] = fma2(q0, kk.x, s2[0][0]);
            s2[0][1] = fma2(q0, kk.y, s2[0][1]);
            s2[1][0] = fma2(q1, kk.x, s2[1][0]);
            s2[1][1] = fma2(q1, kk.y, s2[1][1]);
            s2[2][0] = fma2(q2, kk.x, s2[2][0]);
            s2[2][1] = fma2(q2, kk.y, s2[2][1]);
            s2[3][0] = fma2(q3, kk.x, s2[3][0]);
            s2[3][1] = fma2(q3, kk.y, s2[3][1]);
        }
        float s[4][4];
#pragma unroll
        for (int r = 0; r < 4; ++r) {
            float2 t0 = unpk2(s2[r][0]);
            float2 t1 = unpk2(s2[r][1]);
            s[r][0] = t0.x; s[r][1] = t0.y; s[r][2] = t1.x; s[r][3] = t1.y;
        }

        // ---- online softmax ----
#pragma unroll
        for (int r = 0; r < 4; ++r) {
            int row = r0 + r;
            float rm = fmaxf(fmaxf(s[r][0], s[r][1]), fmaxf(s[r][2], s[r][3]));
            rm = fmaxf(rm, __shfl_xor_sync(0xffffffffu, rm, 8));
            rm = fmaxf(rm, __shfl_xor_sync(0xffffffffu, rm, 4));
            rm = fmaxf(rm, __shfl_xor_sync(0xffffffffu, rm, 2));
            rm = fmaxf(rm, __shfl_xor_sync(0xffffffffu, rm, 1));
            float mo = m_s[row];
            float mn = fmaxf(mo, rm);
            float al = __expf(mo - mn);
            float ps = 0.0f;
#pragma unroll
            for (int c = 0; c < 4; ++c) {
                float p = __expf(s[r][c] - mn);
                Ss[row * 65 + c0 + c] = p;
                ps += p;
            }
            ps += __shfl_xor_sync(0xffffffffu, ps, 8);
            ps += __shfl_xor_sync(0xffffffffu, ps, 4);
            ps += __shfl_xor_sync(0xffffffffu, ps, 2);
            ps += __shfl_xor_sync(0xffffffffu, ps, 1);
            if (tx == 0) {
                m_s[row] = mn;
                al_s[row] = al;
                l_s[row] = l_s[row] * al + ps;
            }
        }
        __syncthreads();  // P + alpha visible

        // ---- O = alpha*O + P V (2x12 per thread, packed) ----
        {
            float a0f = al_s[pr0];
            float a1f = al_s[pr0 + 1];
            unsigned long long aa0 = pack2(a0f, a0f);
            unsigned long long aa1 = pack2(a1f, a1f);
#pragma unroll
            for (int j = 0; j < 6; ++j) {
                acc[j] = mul2(acc[j], aa0);
                acc[6 + j] = mul2(acc[6 + j], aa1);
            }
#pragma unroll 4
            for (int k = 0; k < 64; ++k) {
                float p0 = Ss[pr0 * 65 + k];
                float p1 = Ss[(pr0 + 1) * 65 + k];
                unsigned long long pp0 = pack2(p0, p0);
                unsigned long long pp1 = pack2(p1, p1);
                const ulonglong2* vp = (const ulonglong2*)&Vs[k * 96 + pc0];
                ulonglong2 v0 = vp[0];
                ulonglong2 v1 = vp[1];
                ulonglong2 v2 = vp[2];
                acc[0] = fma2(pp0, v0.x, acc[0]);
                acc[1] = fma2(pp0, v0.y, acc[1]);
                acc[2] = fma2(pp0, v1.x, acc[2]);
                acc[3] = fma2(pp0, v1.y, acc[3]);
                acc[4] = fma2(pp0, v2.x, acc[4]);
                acc[5] = fma2(pp0, v2.y, acc[5]);
                acc[6] = fma2(pp1, v0.x, acc[6]);
                acc[7] = fma2(pp1, v0.y, acc[7]);
                acc[8] = fma2(pp1, v1.x, acc[8]);
                acc[9] = fma2(pp1, v1.y, acc[9]);
                acc[10] = fma2(pp1, v2.x, acc[10]);
                acc[11] = fma2(pp1, v2.y, acc[11]);
            }
        }
    }

    // ---- finalize: O /= l ----
    float inv0 = 1.0f / l_s[pr0];
    float inv1 = 1.0f / l_s[pr0 + 1];
    float4* o0 = (float4*)&g_o[(size_t)(row0g + pr0) * 96 + pc0];
    float4* o1 = (float4*)&g_o[(size_t)(row0g + pr0 + 1) * 96 + pc0];
#pragma unroll
    for (int j = 0; j < 3; ++j) {
        float2 p0 = unpk2(acc[2 * j]);
        float2 p1 = unpk2(acc[2 * j + 1]);
        o0[j] = make_float4(p0.x * inv0, p0.y * inv0, p1.x * inv0, p1.y * inv0);
        float2 q0 = unpk2(acc[6 + 2 * j]);
        float2 q1 = unpk2(acc[6 + 2 * j + 1]);
        o1[j] = make_float4(q0.x * inv1, q0.y * inv1, q1.x * inv1, q1.y * inv1);
    }
}

// ---------------------------------------------------------------------------
// Launch: qkv (3 GEMMs) -> flash attention -> final conv + bias + residual
// ---------------------------------------------------------------------------
extern "C" void kernel_launch(void* const* d_in, const int* in_sizes, int n_in,
                              void* d_out, int out_size) {
    (void)in_sizes; (void)n_in; (void)out_size;
    const float* x = (const float*)d_in[0];
    const float* w1 = (const float*)d_in[1];
    const float* b1 = (const float*)d_in[2];
    const float* w2 = (const float*)d_in[3];
    const float* b2 = (const float*)d_in[4];
    const float* w3 = (const float*)d_in[5];
    const float* b3 = (const float*)d_in[6];
    const float* wl = (const float*)d_in[7];
    const float* bl = (const float*)d_in[8];
    float* out = (float*)d_out;

    void *qp, *kp, *vp, *op;
    cudaGetSymbolAddress(&qp, g_q);
    cudaGetSymbolAddress(&kp, g_k);
    cudaGetSymbolAddress(&vp, g_v);
    cudaGetSymbolAddress(&op, g_o);

    cudaFuncSetAttribute(attn_kernel, cudaFuncAttributeMaxDynamicSharedMemorySize,
                         ATTN_SMEM_BYTES);

    dim3 gqkv(32, 2, 1);
    conv1x1_kernel<192, false><<<gqkv, 256>>>(w1, b1, x, nullptr, (float*)qp, 96);
    conv1x1_kernel<192, false><<<gqkv, 256>>>(w2, b2, x, nullptr, (float*)kp, 96);
    conv1x1_kernel<192, false><<<gqkv, 256>>>(w3, b3, x, nullptr, (float*)vp, 96);

    attn_kernel<<<128, 256, ATTN_SMEM_BYTES>>>();

    dim3 gfin(32, 2, 2);
    conv1x1_kernel<96, true><<<gfin, 256>>>(wl, bl, (const float*)op, x, out, 192);
}

// round 5
// speedup vs baseline: 3.9420x; 3.9372x over previous
#include <cuda_runtime.h>
#include <cuda_bf16.h>
#include <cstdint>

#define DEVFN __device__ __forceinline__

// ===========================================================================
// f32x2 helpers (conv GEMMs)
// ===========================================================================
DEVFN unsigned long long pack2(float lo, float hi) {
    unsigned long long r;
    asm("mov.b64 %0, {%1, %2};" : "=l"(r) : "f"(lo), "f"(hi));
    return r;
}
DEVFN unsigned long long fma2(unsigned long long a, unsigned long long b,
                              unsigned long long c) {
    unsigned long long d;
    asm("fma.rn.f32x2 %0, %1, %2, %3;" : "=l"(d) : "l"(a), "l"(b), "l"(c));
    return d;
}
DEVFN float2 unpk2(unsigned long long v) {
    float2 f;
    asm("mov.b64 {%0, %1}, %2;" : "=f"(f.x), "=f"(f.y) : "l"(v));
    return f;
}

// ===========================================================================
// bf16 + mma.sync + ldmatrix helpers (baseline sm_80+ features; compile clean
// for plain sm_100 — no tcgen05 / 100a-only instructions anywhere)
// ===========================================================================
DEVFN uint32_t smem_u32(const void* p) {
    uint32_t a;
    asm("{ .reg .u64 t; cvta.to.shared.u64 t, %1; cvt.u32.u64 %0, t; }"
        : "=r"(a) : "l"(p));
    return a;
}
DEVFN uint32_t packbf(float x0, float x1) {  // lo half = x0, hi half = x1
    uint32_t r;
    asm("cvt.rn.satfinite.bf16x2.f32 %0, %1, %2;" : "=r"(r) : "f"(x1), "f"(x0));
    return r;
}
DEVFN float bf16rt(float x) { return __bfloat162float(__float2bfloat16_rn(x)); }

DEVFN void ldsm4(uint32_t& r0, uint32_t& r1, uint32_t& r2, uint32_t& r3,
                 uint32_t addr) {
    asm volatile("ldmatrix.sync.aligned.m8n8.x4.shared.b16 {%0,%1,%2,%3}, [%4];"
                 : "=r"(r0), "=r"(r1), "=r"(r2), "=r"(r3) : "r"(addr));
}
DEVFN void ldsm4t(uint32_t& r0, uint32_t& r1, uint32_t& r2, uint32_t& r3,
                  uint32_t addr) {
    asm volatile("ldmatrix.sync.aligned.m8n8.x4.trans.shared.b16 {%0,%1,%2,%3}, [%4];"
                 : "=r"(r0), "=r"(r1), "=r"(r2), "=r"(r3) : "r"(addr));
}
DEVFN void mma16816(float* d, const uint32_t* a, uint32_t b0, uint32_t b1) {
    asm volatile(
        "mma.sync.aligned.m16n8k16.row.col.f32.bf16.bf16.f32 "
        "{%0,%1,%2,%3}, {%4,%5,%6,%7}, {%8,%9}, {%0,%1,%2,%3};"
        : "+f"(d[0]), "+f"(d[1]), "+f"(d[2]), "+f"(d[3])
        : "r"(a[0]), "r"(a[1]), "r"(a[2]), "r"(a[3]), "r"(b0), "r"(b1));
}

// ===========================================================================
// Scratch
// ===========================================================================
__device__ float g_q[786432];
__device__ float g_k[786432];
__device__ float g_v[786432];
__device__ float g_o[786432];
__device__ float g_opart[1572864];     // [2][8192][96] unnormalized O
__device__ float g_ml[32768];          // [2][8192][2] (m, l)
// Padded bf16 hi/lo tile images: [64 tiles][2(hi,lo)][128 rows][104 ch] halves
__device__ uint32_t g_kpad[851968];    // 64 * 13312 u32
__device__ uint32_t g_vpad[851968];

#define PITCH 104                       /* halves per row (208 B, 16B-aligned) */
#define TILE_U32 13312                  /* u32 per (hi+lo) tile image          */
#define HALF_OFF_B 26624                /* byte offset hi -> lo block in smem  */
#define ATTN_SMEM_B 106496              /* K image 53248 + V image 53248       */

// ===========================================================================
// conv1x1 GEMM (proven)
// ===========================================================================
template <int KDIM, bool RESID>
__global__ __launch_bounds__(256) void conv1x1_kernel(
    const float* __restrict__ A, const float* __restrict__ bias,
    const float* __restrict__ B, const float* __restrict__ R,
    float* __restrict__ C, int Mtot) {
    __shared__ float AsT[16][98];
    __shared__ float Bs[16][128];
    const int tid = threadIdx.x;
    const int tx = tid & 15;
    const int ty = tid >> 4;
    const int mo = blockIdx.z * 96;
    const int b = blockIdx.y;
    const int n0 = blockIdx.x * 128;
    const float* Ab = A + (size_t)mo * KDIM;
    const float* Bb = B + (size_t)b * KDIM * 4096 + n0;
    const int r0 = ty * 6;
    const int c0 = tx * 8;
    unsigned long long acc[6][4];
#pragma unroll
    for (int r = 0; r < 6; ++r)
#pragma unroll
        for (int j = 0; j < 4; ++j) acc[r][j] = 0ULL;
    for (int kc = 0; kc < KDIM; kc += 16) {
        __syncthreads();
        for (int i = tid; i < 96 * 16; i += 256) {
            int k = i & 15, r = i >> 4;
            AsT[k][r] = Ab[r * KDIM + kc + k];
        }
        for (int i = tid; i < 16 * 128; i += 256) {
            int n = i & 127, k = i >> 7;
            Bs[k][n] = Bb[(size_t)(kc + k) * 4096 + n];
        }
        __syncthreads();
#pragma unroll
        for (int k = 0; k < 16; ++k) {
            float2 a01 = *(const float2*)&AsT[k][r0];
            float2 a23 = *(const float2*)&AsT[k][r0 + 2];
            float2 a45 = *(const float2*)&AsT[k][r0 + 4];
            ulonglong2 bv0 = *(const ulonglong2*)&Bs[k][c0];
            ulonglong2 bv1 = *(const ulonglong2*)&Bs[k][c0 + 4];
            float av[6] = {a01.x, a01.y, a23.x, a23.y, a45.x, a45.y};
#pragma unroll
            for (int r = 0; r < 6; ++r) {
                unsigned long long ap = pack2(av[r], av[r]);
                acc[r][0] = fma2(ap, bv0.x, acc[r][0]);
                acc[r][1] = fma2(ap, bv0.y, acc[r][1]);
                acc[r][2] = fma2(ap, bv1.x, acc[r][2]);
                acc[r][3] = fma2(ap, bv1.y, acc[r][3]);
            }
        }
    }
#pragma unroll
    for (int r = 0; r < 6; ++r) {
        int m = mo + r0 + r;
        float bv = bias[m];
        size_t base = ((size_t)b * Mtot + m) * 4096 + n0 + c0;
        float o[8];
#pragma unroll
        for (int j = 0; j < 4; ++j) {
            float2 t = unpk2(acc[r][j]);
            o[2 * j] = t.x + bv;
            o[2 * j + 1] = t.y + bv;
        }
        if (RESID) {
            float4 rA = *(const float4*)&R[base];
            float4 rB = *(const float4*)&R[base + 4];
            o[0] += rA.x; o[1] += rA.y; o[2] += rA.z; o[3] += rA.w;
            o[4] += rB.x; o[5] += rB.y; o[6] += rB.z; o[7] += rB.w;
        }
        *(float4*)&C[base] = make_float4(o[0], o[1], o[2], o[3]);
        *(float4*)&C[base + 4] = make_float4(o[4], o[5], o[6], o[7]);
    }
}

// ===========================================================================
// Prep: fp32 [tile][128 rows][96 ch] -> padded bf16 hi/lo image
//       [tile][hi/lo][128][PITCH]. Rows are keys for both K and V.
// ===========================================================================
__global__ __launch_bounds__(256) void prep_pad_kernel(
    const float* __restrict__ src, uint32_t* __restrict__ dst) {
    const int t = blockIdx.x;
    const float* s = src + (size_t)t * 12288;
    uint32_t* dhi = dst + (size_t)t * TILE_U32;
    uint32_t* dlo = dhi + 6656;
    for (int i = threadIdx.x; i < 6656; i += 256) {   // 128 rows * 52 u32
        int r = i / 52, j = i - r * 52, c = 2 * j;
        float x0 = 0.0f, x1 = 0.0f;
        if (c < 96) {
            float2 v = *(const float2*)&s[r * 96 + c];
            x0 = v.x; x1 = v.y;
        }
        dhi[i] = packbf(x0, x1);
        dlo[i] = packbf(x0 - bf16rt(x0), x1 - bf16rt(x1));
    }
}

// ===========================================================================
// mma.sync flash attention. grid = 128 (qblk*2 + khalf), 256 threads, 8 warps.
// Warp owns 16 query rows. Key tiles of 128. 3-pass bf16-split GEMMs.
// ===========================================================================
__global__ __launch_bounds__(256, 1) void attn_mma_kernel() {
    extern __shared__ __align__(16) char smraw[];
    const int tid = threadIdx.x;
    const int lane = tid & 31;
    const int w = tid >> 5;
    const int qblk = blockIdx.x >> 1;
    const int khalf = blockIdx.x & 1;

    const int rquad = lane >> 2;        // 0..7
    const int c2 = 2 * (lane & 3);      // 0,2,4,6
    const int rowg0 = qblk * 128 + w * 16 + rquad;
    const int rowg1 = rowg0 + 8;

    // ldmatrix per-lane base addresses
    const uint32_t sbase = smem_u32(smraw);
    const int g = lane >> 3, j8 = lane & 7;
    const uint32_t kfb = sbase +
        2u * (uint32_t)((j8 + ((g >> 1) & 1) * 8) * PITCH + (g & 1) * 8);
    const uint32_t vfb = sbase + 53248u +
        2u * (uint32_t)((j8 + (g & 1) * 8) * PITCH + ((g >> 1) & 1) * 8);

    // ---- Q fragments (hi/lo), resident for the whole kernel ----
    uint32_t Qh[6][4], Ql[6][4];
#pragma unroll
    for (int s = 0; s < 6; ++s) {
        const float* q0 = &g_q[(size_t)rowg0 * 96 + s * 16 + c2];
        const float* q1 = &g_q[(size_t)rowg1 * 96 + s * 16 + c2];
        float2 x0 = *(const float2*)q0;
        float2 x1 = *(const float2*)q1;
        float2 x2 = *(const float2*)(q0 + 8);
        float2 x3 = *(const float2*)(q1 + 8);
        Qh[s][0] = packbf(x0.x, x0.y);
        Qh[s][1] = packbf(x1.x, x1.y);
        Qh[s][2] = packbf(x2.x, x2.y);
        Qh[s][3] = packbf(x3.x, x3.y);
        Ql[s][0] = packbf(x0.x - bf16rt(x0.x), x0.y - bf16rt(x0.y));
        Ql[s][1] = packbf(x1.x - bf16rt(x1.x), x1.y - bf16rt(x1.y));
        Ql[s][2] = packbf(x2.x - bf16rt(x2.x), x2.y - bf16rt(x2.y));
        Ql[s][3] = packbf(x3.x - bf16rt(x3.x), x3.y - bf16rt(x3.y));
    }

    float m0 = __int_as_float(0xff800000), m1 = m0;
    float l0 = 0.0f, l1 = 0.0f;
    float accO[12][4];
#pragma unroll
    for (int n = 0; n < 12; ++n)
#pragma unroll
        for (int j = 0; j < 4; ++j) accO[n][j] = 0.0f;

    for (int it = 0; it < 32; ++it) {
        const int tile = khalf * 32 + it;
        __syncthreads();  // all warps done reading smem from previous tile
        {
            const uint4* ks = (const uint4*)g_kpad + (size_t)tile * 3328;
            const uint4* vs = (const uint4*)g_vpad + (size_t)tile * 3328;
            uint4* kd = (uint4*)smraw;
            uint4* vd = (uint4*)(smraw + 53248);
#pragma unroll
            for (int i = 0; i < 13; ++i) kd[tid + 256 * i] = ks[tid + 256 * i];
#pragma unroll
            for (int i = 0; i < 13; ++i) vd[tid + 256 * i] = vs[tid + 256 * i];
        }
        __syncthreads();

        // ---- S = Q K^T : 16 n-tiles x 6 k-steps x 3 passes ----
        float accS[16][4];
#pragma unroll
        for (int t = 0; t < 16; ++t)
#pragma unroll
            for (int j = 0; j < 4; ++j) accS[t][j] = 0.0f;
#pragma unroll
        for (int p = 0; p < 8; ++p) {
#pragma unroll
            for (int s = 0; s < 6; ++s) {
                uint32_t ka = kfb + 2u * (uint32_t)(p * 16 * PITCH + s * 16);
                uint32_t h0, h1, h2, h3, e0, e1, e2, e3;
                ldsm4(h0, h1, h2, h3, ka);
                ldsm4(e0, e1, e2, e3, ka + HALF_OFF_B);
                mma16816(accS[2 * p], Qh[s], h0, h1);
                mma16816(accS[2 * p + 1], Qh[s], h2, h3);
                mma16816(accS[2 * p], Qh[s], e0, e1);
                mma16816(accS[2 * p + 1], Qh[s], e2, e3);
                mma16816(accS[2 * p], Ql[s], h0, h1);
                mma16816(accS[2 * p + 1], Ql[s], h2, h3);
            }
        }

        // ---- online softmax (rows r0, r1 per thread; quad = 4 lanes/row) ----
        float mx0 = __int_as_float(0xff800000), mx1 = mx0;
#pragma unroll
        for (int t = 0; t < 16; ++t) {
            mx0 = fmaxf(mx0, fmaxf(accS[t][0], accS[t][1]));
            mx1 = fmaxf(mx1, fmaxf(accS[t][2], accS[t][3]));
        }
        mx0 = fmaxf(mx0, __shfl_xor_sync(0xffffffffu, mx0, 1));
        mx0 = fmaxf(mx0, __shfl_xor_sync(0xffffffffu, mx0, 2));
        mx1 = fmaxf(mx1, __shfl_xor_sync(0xffffffffu, mx1, 1));
        mx1 = fmaxf(mx1, __shfl_xor_sync(0xffffffffu, mx1, 2));
        float mn0 = fmaxf(m0, mx0), mn1 = fmaxf(m1, mx1);
        float al0 = __expf(m0 - mn0), al1 = __expf(m1 - mn1);

        uint32_t Ph[8][4], Pl[8][4];
        float sum0 = 0.0f, sum1 = 0.0f;
#pragma unroll
        for (int t = 0; t < 16; ++t) {
            float p0 = __expf(accS[t][0] - mn0);
            float p1 = __expf(accS[t][1] - mn0);
            float p2 = __expf(accS[t][2] - mn1);
            float p3 = __expf(accS[t][3] - mn1);
            sum0 += p0 + p1;
            sum1 += p2 + p3;
            int j = t >> 1;
            int rr = (t & 1) * 2;
            Ph[j][rr] = packbf(p0, p1);
            Ph[j][rr + 1] = packbf(p2, p3);
            Pl[j][rr] = packbf(p0 - bf16rt(p0), p1 - bf16rt(p1));
            Pl[j][rr + 1] = packbf(p2 - bf16rt(p2), p3 - bf16rt(p3));
        }
        sum0 += __shfl_xor_sync(0xffffffffu, sum0, 1);
        sum0 += __shfl_xor_sync(0xffffffffu, sum0, 2);
        sum1 += __shfl_xor_sync(0xffffffffu, sum1, 1);
        sum1 += __shfl_xor_sync(0xffffffffu, sum1, 2);
        l0 = l0 * al0 + sum0;
        l1 = l1 * al1 + sum1;
        m0 = mn0;
        m1 = mn1;

        // ---- O = al*O + P V : 12 n-tiles x 8 k-steps x 3 passes ----
#pragma unroll
        for (int n = 0; n < 12; ++n) {
            accO[n][0] *= al0;
            accO[n][1] *= al0;
            accO[n][2] *= al1;
            accO[n][3] *= al1;
        }
#pragma unroll
        for (int s = 0; s < 8; ++s) {
#pragma unroll
            for (int p = 0; p < 6; ++p) {
                uint32_t va = vfb + 2u * (uint32_t)(s * 16 * PITCH + p * 16);
                uint32_t h0, h1, h2, h3, e0, e1, e2, e3;
                ldsm4t(h0, h1, h2, h3, va);
                ldsm4t(e0, e1, e2, e3, va + HALF_OFF_B);
                mma16816(accO[2 * p], Ph[s], h0, h1);
                mma16816(accO[2 * p + 1], Ph[s], h2, h3);
                mma16816(accO[2 * p], Ph[s], e0, e1);
                mma16816(accO[2 * p + 1], Ph[s], e2, e3);
                mma16816(accO[2 * p], Pl[s], h0, h1);
                mma16816(accO[2 * p + 1], Pl[s], h2, h3);
            }
        }
    }

    // ---- write partials ----
    float* op = g_opart + (size_t)khalf * 786432;
#pragma unroll
    for (int n = 0; n < 12; ++n) {
        int col = n * 8 + c2;
        *(float2*)&op[(size_t)rowg0 * 96 + col] = make_float2(accO[n][0], accO[n][1]);
        *(float2*)&op[(size_t)rowg1 * 96 + col] = make_float2(accO[n][2], accO[n][3]);
    }
    if ((lane & 3) == 0) {
        ((float2*)g_ml)[(size_t)khalf * 8192 + rowg0] = make_float2(m0, l0);
        ((float2*)g_ml)[(size_t)khalf * 8192 + rowg1] = make_float2(m1, l1);
    }
}

// ===========================================================================
// Combine the two key-half partials
// ===========================================================================
__global__ __launch_bounds__(96) void combine_kernel() {
    int r = blockIdx.x;
    int c = threadIdx.x;
    float2 ml0 = ((const float2*)g_ml)[r];
    float2 ml1 = ((const float2*)g_ml)[8192 + r];
    float M = fmaxf(ml0.x, ml1.x);
    float w0 = __expf(ml0.x - M);
    float w1 = __expf(ml1.x - M);
    float inv = 1.0f / (w0 * ml0.y + w1 * ml1.y);
    size_t idx = (size_t)r * 96 + c;
    g_o[idx] = (w0 * g_opart[idx] + w1 * g_opart[786432 + idx]) * inv;
}

// ===========================================================================
// Launch
// ===========================================================================
extern "C" void kernel_launch(void* const* d_in, const int* in_sizes, int n_in,
                              void* d_out, int out_size) {
    (void)in_sizes; (void)n_in; (void)out_size;
    const float* x = (const float*)d_in[0];
    const float* w1 = (const float*)d_in[1];
    const float* b1 = (const float*)d_in[2];
    const float* w2 = (const float*)d_in[3];
    const float* b2 = (const float*)d_in[4];
    const float* w3 = (const float*)d_in[5];
    const float* b3 = (const float*)d_in[6];
    const float* wl = (const float*)d_in[7];
    const float* bl = (const float*)d_in[8];
    float* out = (float*)d_out;

    void *qp, *kp, *vp, *op, *kpp, *vpp;
    cudaGetSymbolAddress(&qp, g_q);
    cudaGetSymbolAddress(&kp, g_k);
    cudaGetSymbolAddress(&vp, g_v);
    cudaGetSymbolAddress(&op, g_o);
    cudaGetSymbolAddress(&kpp, g_kpad);
    cudaGetSymbolAddress(&vpp, g_vpad);

    cudaFuncSetAttribute(attn_mma_kernel,
                         cudaFuncAttributeMaxDynamicSharedMemorySize, ATTN_SMEM_B);

    dim3 gqkv(32, 2, 1);
    conv1x1_kernel<192, false><<<gqkv, 256>>>(w1, b1, x, nullptr, (float*)qp, 96);
    conv1x1_kernel<192, false><<<gqkv, 256>>>(w2, b2, x, nullptr, (float*)kp, 96);
    conv1x1_kernel<192, false><<<gqkv, 256>>>(w3, b3, x, nullptr, (float*)vp, 96);

    prep_pad_kernel<<<64, 256>>>((const float*)kp, (uint32_t*)kpp);
    prep_pad_kernel<<<64, 256>>>((const float*)vp, (uint32_t*)vpp);

    attn_mma_kernel<<<128, 256, ATTN_SMEM_B>>>();

    combine_kernel<<<8192, 96>>>();

    dim3 gfin(32, 2, 2);
    conv1x1_kernel<96, true><<<gfin, 256>>>(wl, bl, (const float*)op, x, out, 192);
}

// round 6
// speedup vs baseline: 5.0807x; 1.2889x over previous
#include <cuda_runtime.h>
#include <cuda_bf16.h>
#include <cstdint>

#define DEVFN __device__ __forceinline__

// ===========================================================================
// f32x2 helpers (conv GEMMs)
// ===========================================================================
DEVFN unsigned long long pack2(float lo, float hi) {
    unsigned long long r;
    asm("mov.b64 %0, {%1, %2};" : "=l"(r) : "f"(lo), "f"(hi));
    return r;
}
DEVFN unsigned long long fma2(unsigned long long a, unsigned long long b,
                              unsigned long long c) {
    unsigned long long d;
    asm("fma.rn.f32x2 %0, %1, %2, %3;" : "=l"(d) : "l"(a), "l"(b), "l"(c));
    return d;
}
DEVFN float2 unpk2(unsigned long long v) {
    float2 f;
    asm("mov.b64 {%0, %1}, %2;" : "=f"(f.x), "=f"(f.y) : "l"(v));
    return f;
}

// ===========================================================================
// bf16 + mma.sync + ldmatrix + cp.async helpers (all baseline sm_80+)
// ===========================================================================
DEVFN uint32_t smem_u32(const void* p) {
    uint32_t a;
    asm("{ .reg .u64 t; cvta.to.shared.u64 t, %1; cvt.u32.u64 %0, t; }"
        : "=r"(a) : "l"(p));
    return a;
}
DEVFN uint32_t packbf(float x0, float x1) {  // lo half = x0, hi half = x1
    uint32_t r;
    asm("cvt.rn.satfinite.bf16x2.f32 %0, %1, %2;" : "=r"(r) : "f"(x1), "f"(x0));
    return r;
}
DEVFN float bf16rt(float x) { return __bfloat162float(__float2bfloat16_rn(x)); }

DEVFN void ldsm4(uint32_t& r0, uint32_t& r1, uint32_t& r2, uint32_t& r3,
                 uint32_t addr) {
    asm volatile("ldmatrix.sync.aligned.m8n8.x4.shared.b16 {%0,%1,%2,%3}, [%4];"
                 : "=r"(r0), "=r"(r1), "=r"(r2), "=r"(r3) : "r"(addr));
}
DEVFN void ldsm4t(uint32_t& r0, uint32_t& r1, uint32_t& r2, uint32_t& r3,
                  uint32_t addr) {
    asm volatile("ldmatrix.sync.aligned.m8n8.x4.trans.shared.b16 {%0,%1,%2,%3}, [%4];"
                 : "=r"(r0), "=r"(r1), "=r"(r2), "=r"(r3) : "r"(addr));
}
DEVFN void mma16816(float* d, const uint32_t* a, uint32_t b0, uint32_t b1) {
    asm volatile(
        "mma.sync.aligned.m16n8k16.row.col.f32.bf16.bf16.f32 "
        "{%0,%1,%2,%3}, {%4,%5,%6,%7}, {%8,%9}, {%0,%1,%2,%3};"
        : "+f"(d[0]), "+f"(d[1]), "+f"(d[2]), "+f"(d[3])
        : "r"(a[0]), "r"(a[1]), "r"(a[2]), "r"(a[3]), "r"(b0), "r"(b1));
}
DEVFN void cpasync16(uint32_t dst, const void* src) {
    asm volatile("cp.async.cg.shared.global [%0], [%1], 16;"
                 :: "r"(dst), "l"(src));
}
#define CP_COMMIT() asm volatile("cp.async.commit_group;" ::: "memory")
#define CP_WAIT0() asm volatile("cp.async.wait_group 0;" ::: "memory")

// ===========================================================================
// Scratch
// ===========================================================================
__device__ float g_q[786432];
__device__ float g_o[786432];
__device__ float g_opart[1572864];     // [2][8192][96] unnormalized O
__device__ float g_ml[32768];          // [2][8192][2] (m, l)
// Padded bf16 hi/lo tile images: [64 tiles][hi|lo][128 rows][104 ch] halves
__device__ uint32_t g_kpad[851968];    // 64 * 13312 u32
__device__ uint32_t g_vpad[851968];

#define PITCH 104                       /* halves per image row (208 B)        */
#define TILE_U32 13312                  /* u32 per (hi+lo) tile image          */
#define HALF_OFF_B 26624                /* byte offset hi -> lo block          */
#define KBUF_B 53248                    /* one tile image in smem              */
#define ATTN_SMEM_B (3 * KBUF_B)        /* K ping + K pong + V = 159744 B      */

// ===========================================================================
// Fused QKV conv: grid (32, 2, 3). z=0 -> Q (fp32), z=1 -> K image, z=2 -> V.
// Epilogue for z>0 writes bf16 hi/lo padded tile images directly (prep fused).
// ===========================================================================
__global__ __launch_bounds__(256) void qkv_conv_kernel(
    const float* __restrict__ x,
    const float* __restrict__ w1, const float* __restrict__ b1,
    const float* __restrict__ w2, const float* __restrict__ b2,
    const float* __restrict__ w3, const float* __restrict__ b3) {
    __shared__ float AsT[16][98];
    __shared__ float Bs[16][128];
    const int tid = threadIdx.x;
    const int tx = tid & 15;
    const int ty = tid >> 4;
    const int b = blockIdx.y;
    const int z = blockIdx.z;
    const int n0 = blockIdx.x * 128;
    const float* A = (z == 0) ? w1 : (z == 1) ? w2 : w3;
    const float* bias = (z == 0) ? b1 : (z == 1) ? b2 : b3;
    const float* Bb = x + (size_t)b * 192 * 4096 + n0;
    const int r0 = ty * 6;
    const int c0 = tx * 8;

    unsigned long long acc[6][4];
#pragma unroll
    for (int r = 0; r < 6; ++r)
#pragma unroll
        for (int j = 0; j < 4; ++j) acc[r][j] = 0ULL;

    for (int kc = 0; kc < 192; kc += 16) {
        __syncthreads();
        for (int i = tid; i < 96 * 16; i += 256) {
            int k = i & 15, r = i >> 4;
            AsT[k][r] = A[r * 192 + kc + k];
        }
        for (int i = tid; i < 16 * 128; i += 256) {
            int n = i & 127, k = i >> 7;
            Bs[k][n] = Bb[(size_t)(kc + k) * 4096 + n];
        }
        __syncthreads();
#pragma unroll
        for (int k = 0; k < 16; ++k) {
            float2 a01 = *(const float2*)&AsT[k][r0];
            float2 a23 = *(const float2*)&AsT[k][r0 + 2];
            float2 a45 = *(const float2*)&AsT[k][r0 + 4];
            ulonglong2 bv0 = *(const ulonglong2*)&Bs[k][c0];
            ulonglong2 bv1 = *(const ulonglong2*)&Bs[k][c0 + 4];
            float av[6] = {a01.x, a01.y, a23.x, a23.y, a45.x, a45.y};
#pragma unroll
            for (int r = 0; r < 6; ++r) {
                unsigned long long ap = pack2(av[r], av[r]);
                acc[r][0] = fma2(ap, bv0.x, acc[r][0]);
                acc[r][1] = fma2(ap, bv0.y, acc[r][1]);
                acc[r][2] = fma2(ap, bv1.x, acc[r][2]);
                acc[r][3] = fma2(ap, bv1.y, acc[r][3]);
            }
        }
    }

    uint32_t* img = (z == 1) ? g_kpad : g_vpad;
#pragma unroll
    for (int r = 0; r < 6; ++r) {
        int m = r0 + r;
        float bv = bias[m];
        int f = b * 393216 + m * 4096 + n0 + c0;  // flat index, 8 consecutive
        float o[8];
#pragma unroll
        for (int j = 0; j < 4; ++j) {
            float2 t = unpk2(acc[r][j]);
            o[2 * j] = t.x + bv;
            o[2 * j + 1] = t.y + bv;
        }
        if (z == 0) {
            *(float4*)&g_q[f] = make_float4(o[0], o[1], o[2], o[3]);
            *(float4*)&g_q[f + 4] = make_float4(o[4], o[5], o[6], o[7]);
        } else {
            // raw-reshape: attn row = f/96, ch = f%96 (f even -> pair aligned)
#pragma unroll
            for (int j = 0; j < 4; ++j) {
                int f2 = f + 2 * j;
                int row = f2 / 96;
                int ch = f2 - row * 96;
                uint32_t* d = img + (row >> 7) * TILE_U32 + (row & 127) * 52 +
                              (ch >> 1);
                float x0 = o[2 * j], x1 = o[2 * j + 1];
                d[0] = packbf(x0, x1);
                d[6656] = packbf(x0 - bf16rt(x0), x1 - bf16rt(x1));
            }
        }
    }
}

// ===========================================================================
// Final conv1x1 + bias + residual (proven)
// ===========================================================================
template <int KDIM, bool RESID>
__global__ __launch_bounds__(256) void conv1x1_kernel(
    const float* __restrict__ A, const float* __restrict__ bias,
    const float* __restrict__ B, const float* __restrict__ R,
    float* __restrict__ C, int Mtot) {
    __shared__ float AsT[16][98];
    __shared__ float Bs[16][128];
    const int tid = threadIdx.x;
    const int tx = tid & 15;
    const int ty = tid >> 4;
    const int mo = blockIdx.z * 96;
    const int b = blockIdx.y;
    const int n0 = blockIdx.x * 128;
    const float* Ab = A + (size_t)mo * KDIM;
    const float* Bb = B + (size_t)b * KDIM * 4096 + n0;
    const int r0 = ty * 6;
    const int c0 = tx * 8;
    unsigned long long acc[6][4];
#pragma unroll
    for (int r = 0; r < 6; ++r)
#pragma unroll
        for (int j = 0; j < 4; ++j) acc[r][j] = 0ULL;
    for (int kc = 0; kc < KDIM; kc += 16) {
        __syncthreads();
        for (int i = tid; i < 96 * 16; i += 256) {
            int k = i & 15, r = i >> 4;
            AsT[k][r] = Ab[r * KDIM + kc + k];
        }
        for (int i = tid; i < 16 * 128; i += 256) {
            int n = i & 127, k = i >> 7;
            Bs[k][n] = Bb[(size_t)(kc + k) * 4096 + n];
        }
        __syncthreads();
#pragma unroll
        for (int k = 0; k < 16; ++k) {
            float2 a01 = *(const float2*)&AsT[k][r0];
            float2 a23 = *(const float2*)&AsT[k][r0 + 2];
            float2 a45 = *(const float2*)&AsT[k][r0 + 4];
            ulonglong2 bv0 = *(const ulonglong2*)&Bs[k][c0];
            ulonglong2 bv1 = *(const ulonglong2*)&Bs[k][c0 + 4];
            float av[6] = {a01.x, a01.y, a23.x, a23.y, a45.x, a45.y};
#pragma unroll
            for (int r = 0; r < 6; ++r) {
                unsigned long long ap = pack2(av[r], av[r]);
                acc[r][0] = fma2(ap, bv0.x, acc[r][0]);
                acc[r][1] = fma2(ap, bv0.y, acc[r][1]);
                acc[r][2] = fma2(ap, bv1.x, acc[r][2]);
                acc[r][3] = fma2(ap, bv1.y, acc[r][3]);
            }
        }
    }
#pragma unroll
    for (int r = 0; r < 6; ++r) {
        int m = mo + r0 + r;
        float bv = bias[m];
        size_t base = ((size_t)b * Mtot + m) * 4096 + n0 + c0;
        float o[8];
#pragma unroll
        for (int j = 0; j < 4; ++j) {
            float2 t = unpk2(acc[r][j]);
            o[2 * j] = t.x + bv;
            o[2 * j + 1] = t.y + bv;
        }
        if (RESID) {
            float4 rA = *(const float4*)&R[base];
            float4 rB = *(const float4*)&R[base + 4];
            o[0] += rA.x; o[1] += rA.y; o[2] += rA.z; o[3] += rA.w;
            o[4] += rB.x; o[5] += rB.y; o[6] += rB.z; o[7] += rB.w;
        }
        *(float4*)&C[base] = make_float4(o[0], o[1], o[2], o[3]);
        *(float4*)&C[base + 4] = make_float4(o[4], o[5], o[6], o[7]);
    }
}

// ===========================================================================
// mma.sync flash attention with cp.async pipelining.
// grid = 128 (qblk*2 + khalf), 256 threads, 8 warps, 16 q-rows/warp.
// smem: K ping-pong (2 x 52KB) + V (52KB). V copy overlaps S-phase,
// K(i+1) copy overlaps PV-phase.
// ===========================================================================
__global__ __launch_bounds__(256, 1) void attn_mma_kernel() {
    extern __shared__ __align__(16) char smraw[];
    const int tid = threadIdx.x;
    const int lane = tid & 31;
    const int w = tid >> 5;
    const int qblk = blockIdx.x >> 1;
    const int khalf = blockIdx.x & 1;

    const int rquad = lane >> 2;
    const int c2 = 2 * (lane & 3);
    const int rowg0 = qblk * 128 + w * 16 + rquad;
    const int rowg1 = rowg0 + 8;

    const uint32_t sbase = smem_u32(smraw);
    const int g = lane >> 3, j8 = lane & 7;
    const uint32_t k_lane =
        2u * (uint32_t)((j8 + ((g >> 1) & 1) * 8) * PITCH + (g & 1) * 8);
    const uint32_t v_lane =
        2u * (uint32_t)((j8 + (g & 1) * 8) * PITCH + ((g >> 1) & 1) * 8);
    const uint32_t kbase0 = sbase;
    const uint32_t kbase1 = sbase + KBUF_B;
    const uint32_t vbase = sbase + 2 * KBUF_B;

    // ---- Q fragments (hi/lo), resident ----
    uint32_t Qh[6][4], Ql[6][4];
#pragma unroll
    for (int s = 0; s < 6; ++s) {
        const float* q0 = &g_q[(size_t)rowg0 * 96 + s * 16 + c2];
        const float* q1 = &g_q[(size_t)rowg1 * 96 + s * 16 + c2];
        float2 x0 = *(const float2*)q0;
        float2 x1 = *(const float2*)q1;
        float2 x2 = *(const float2*)(q0 + 8);
        float2 x3 = *(const float2*)(q1 + 8);
        Qh[s][0] = packbf(x0.x, x0.y);
        Qh[s][1] = packbf(x1.x, x1.y);
        Qh[s][2] = packbf(x2.x, x2.y);
        Qh[s][3] = packbf(x3.x, x3.y);
        Ql[s][0] = packbf(x0.x - bf16rt(x0.x), x0.y - bf16rt(x0.y));
        Ql[s][1] = packbf(x1.x - bf16rt(x1.x), x1.y - bf16rt(x1.y));
        Ql[s][2] = packbf(x2.x - bf16rt(x2.x), x2.y - bf16rt(x2.y));
        Ql[s][3] = packbf(x3.x - bf16rt(x3.x), x3.y - bf16rt(x3.y));
    }

    float m0 = __int_as_float(0xff800000), m1 = m0;
    float l0 = 0.0f, l1 = 0.0f;
    float accO[12][4];
#pragma unroll
    for (int n = 0; n < 12; ++n)
#pragma unroll
        for (int j = 0; j < 4; ++j) accO[n][j] = 0.0f;

    // ---- prologue: async-copy K tile 0 ----
    {
        const uint4* ks = (const uint4*)g_kpad + (size_t)(khalf * 32) * 3328;
#pragma unroll
        for (int i = 0; i < 13; ++i)
            cpasync16(kbase0 + 16u * (tid + 256 * i), ks + tid + 256 * i);
        CP_COMMIT();
    }

    for (int it = 0; it < 32; ++it) {
        const int tile = khalf * 32 + it;
        const uint32_t kcur = (it & 1) ? kbase1 : kbase0;

        CP_WAIT0();          // K_it landed (this thread's groups drained)
        __syncthreads();     // all threads' copies visible; prev PV done with V

        // ---- kick V_it copy (overlaps S-phase) ----
        {
            const uint4* vs = (const uint4*)g_vpad + (size_t)tile * 3328;
#pragma unroll
            for (int i = 0; i < 13; ++i)
                cpasync16(vbase + 16u * (tid + 256 * i), vs + tid + 256 * i);
            CP_COMMIT();
        }

        // ---- S = Q K^T : 16 n-tiles x 6 k-steps x 3 passes ----
        float accS[16][4];
#pragma unroll
        for (int t = 0; t < 16; ++t)
#pragma unroll
            for (int j = 0; j < 4; ++j) accS[t][j] = 0.0f;
#pragma unroll
        for (int p = 0; p < 8; ++p) {
#pragma unroll
            for (int s = 0; s < 6; ++s) {
                uint32_t ka = kcur + k_lane +
                              2u * (uint32_t)(p * 16 * PITCH + s * 16);
                uint32_t h0, h1, h2, h3, e0, e1, e2, e3;
                ldsm4(h0, h1, h2, h3, ka);
                ldsm4(e0, e1, e2, e3, ka + HALF_OFF_B);
                mma16816(accS[2 * p], Qh[s], h0, h1);
                mma16816(accS[2 * p + 1], Qh[s], h2, h3);
                mma16816(accS[2 * p], Qh[s], e0, e1);
                mma16816(accS[2 * p + 1], Qh[s], e2, e3);
                mma16816(accS[2 * p], Ql[s], h0, h1);
                mma16816(accS[2 * p + 1], Ql[s], h2, h3);
            }
        }

        CP_WAIT0();          // V_it landed
        __syncthreads();

        // ---- kick K_{it+1} copy (overlaps softmax + PV-phase) ----
        if (it < 31) {
            const uint4* ks = (const uint4*)g_kpad + (size_t)(tile + 1) * 3328;
            const uint32_t knext = (it & 1) ? kbase0 : kbase1;
#pragma unroll
            for (int i = 0; i < 13; ++i)
                cpasync16(knext + 16u * (tid + 256 * i), ks + tid + 256 * i);
            CP_COMMIT();
        }

        // ---- online softmax ----
        float mx0 = __int_as_float(0xff800000), mx1 = mx0;
#pragma unroll
        for (int t = 0; t < 16; ++t) {
            mx0 = fmaxf(mx0, fmaxf(accS[t][0], accS[t][1]));
            mx1 = fmaxf(mx1, fmaxf(accS[t][2], accS[t][3]));
        }
        mx0 = fmaxf(mx0, __shfl_xor_sync(0xffffffffu, mx0, 1));
        mx0 = fmaxf(mx0, __shfl_xor_sync(0xffffffffu, mx0, 2));
        mx1 = fmaxf(mx1, __shfl_xor_sync(0xffffffffu, mx1, 1));
        mx1 = fmaxf(mx1, __shfl_xor_sync(0xffffffffu, mx1, 2));
        float mn0 = fmaxf(m0, mx0), mn1 = fmaxf(m1, mx1);
        float al0 = __expf(m0 - mn0), al1 = __expf(m1 - mn1);

        uint32_t Ph[8][4], Pl[8][4];
        float sum0 = 0.0f, sum1 = 0.0f;
#pragma unroll
        for (int t = 0; t < 16; ++t) {
            float p0 = __expf(accS[t][0] - mn0);
            float p1 = __expf(accS[t][1] - mn0);
            float p2 = __expf(accS[t][2] - mn1);
            float p3 = __expf(accS[t][3] - mn1);
            sum0 += p0 + p1;
            sum1 += p2 + p3;
            int j = t >> 1;
            int rr = (t & 1) * 2;
            Ph[j][rr] = packbf(p0, p1);
            Ph[j][rr + 1] = packbf(p2, p3);
            Pl[j][rr] = packbf(p0 - bf16rt(p0), p1 - bf16rt(p1));
            Pl[j][rr + 1] = packbf(p2 - bf16rt(p2), p3 - bf16rt(p3));
        }
        sum0 += __shfl_xor_sync(0xffffffffu, sum0, 1);
        sum0 += __shfl_xor_sync(0xffffffffu, sum0, 2);
        sum1 += __shfl_xor_sync(0xffffffffu, sum1, 1);
        sum1 += __shfl_xor_sync(0xffffffffu, sum1, 2);
        l0 = l0 * al0 + sum0;
        l1 = l1 * al1 + sum1;
        m0 = mn0;
        m1 = mn1;

        // ---- O = al*O + P V : 12 n-tiles x 8 k-steps x 3 passes ----
#pragma unroll
        for (int n = 0; n < 12; ++n) {
            accO[n][0] *= al0;
            accO[n][1] *= al0;
            accO[n][2] *= al1;
            accO[n][3] *= al1;
        }
#pragma unroll
        for (int s = 0; s < 8; ++s) {
#pragma unroll
            for (int p = 0; p < 6; ++p) {
                uint32_t va = vbase + v_lane +
                              2u * (uint32_t)(s * 16 * PITCH + p * 16);
                uint32_t h0, h1, h2, h3, e0, e1, e2, e3;
                ldsm4t(h0, h1, h2, h3, va);
                ldsm4t(e0, e1, e2, e3, va + HALF_OFF_B);
                mma16816(accO[2 * p], Ph[s], h0, h1);
                mma16816(accO[2 * p + 1], Ph[s], h2, h3);
                mma16816(accO[2 * p], Ph[s], e0, e1);
                mma16816(accO[2 * p + 1], Ph[s], e2, e3);
                mma16816(accO[2 * p], Pl[s], h0, h1);
                mma16816(accO[2 * p + 1], Pl[s], h2, h3);
            }
        }
    }

    // ---- write partials ----
    float* op = g_opart + (size_t)khalf * 786432;
#pragma unroll
    for (int n = 0; n < 12; ++n) {
        int col = n * 8 + c2;
        *(float2*)&op[(size_t)rowg0 * 96 + col] = make_float2(accO[n][0], accO[n][1]);
        *(float2*)&op[(size_t)rowg1 * 96 + col] = make_float2(accO[n][2], accO[n][3]);
    }
    if ((lane & 3) == 0) {
        ((float2*)g_ml)[(size_t)khalf * 8192 + rowg0] = make_float2(m0, l0);
        ((float2*)g_ml)[(size_t)khalf * 8192 + rowg1] = make_float2(m1, l1);
    }
}

// ===========================================================================
// Combine the two key-half partials (coalesced: 8 rows / 768-thread block)
// ===========================================================================
__global__ __launch_bounds__(768) void combine_kernel() {
    int e = blockIdx.x * 768 + threadIdx.x;
    int r = e / 96;
    float2 ml0 = ((const float2*)g_ml)[r];
    float2 ml1 = ((const float2*)g_ml)[8192 + r];
    float M = fmaxf(ml0.x, ml1.x);
    float w0 = __expf(ml0.x - M);
    float w1 = __expf(ml1.x - M);
    float inv = 1.0f / (w0 * ml0.y + w1 * ml1.y);
    g_o[e] = (w0 * g_opart[e] + w1 * g_opart[786432 + e]) * inv;
}

// ===========================================================================
// Launch
// ===========================================================================
extern "C" void kernel_launch(void* const* d_in, const int* in_sizes, int n_in,
                              void* d_out, int out_size) {
    (void)in_sizes; (void)n_in; (void)out_size;
    const float* x = (const float*)d_in[0];
    const float* w1 = (const float*)d_in[1];
    const float* b1 = (const float*)d_in[2];
    const float* w2 = (const float*)d_in[3];
    const float* b2 = (const float*)d_in[4];
    const float* w3 = (const float*)d_in[5];
    const float* b3 = (const float*)d_in[6];
    const float* wl = (const float*)d_in[7];
    const float* bl = (const float*)d_in[8];
    float* out = (float*)d_out;

    void* op;
    cudaGetSymbolAddress(&op, g_o);

    cudaFuncSetAttribute(attn_mma_kernel,
                         cudaFuncAttributeMaxDynamicSharedMemorySize, ATTN_SMEM_B);

    qkv_conv_kernel<<<dim3(32, 2, 3), 256>>>(x, w1, b1, w2, b2, w3, b3);

    attn_mma_kernel<<<128, 256, ATTN_SMEM_B>>>();

    combine_kernel<<<1024, 768>>>();

    dim3 gfin(32, 2, 2);
    conv1x1_kernel<96, true><<<gfin, 256>>>(wl, bl, (const float*)op, x, out, 192);
}

// round 7
// speedup vs baseline: 5.5072x; 1.0840x over previous
#include <cuda_runtime.h>
#include <cuda_bf16.h>
#include <cstdint>

#define DEVFN __device__ __forceinline__

// ===========================================================================
// f32x2 helpers (conv GEMMs)
// ===========================================================================
DEVFN unsigned long long pack2(float lo, float hi) {
    unsigned long long r;
    asm("mov.b64 %0, {%1, %2};" : "=l"(r) : "f"(lo), "f"(hi));
    return r;
}
DEVFN unsigned long long fma2(unsigned long long a, unsigned long long b,
                              unsigned long long c) {
    unsigned long long d;
    asm("fma.rn.f32x2 %0, %1, %2, %3;" : "=l"(d) : "l"(a), "l"(b), "l"(c));
    return d;
}
DEVFN float2 unpk2(unsigned long long v) {
    float2 f;
    asm("mov.b64 {%0, %1}, %2;" : "=f"(f.x), "=f"(f.y) : "l"(v));
    return f;
}

// ===========================================================================
// bf16 + mma.sync + ldmatrix + cp.async helpers (all baseline sm_80+)
// ===========================================================================
DEVFN uint32_t smem_u32(const void* p) {
    uint32_t a;
    asm("{ .reg .u64 t; cvta.to.shared.u64 t, %1; cvt.u32.u64 %0, t; }"
        : "=r"(a) : "l"(p));
    return a;
}
DEVFN uint32_t packbf(float x0, float x1) {  // lo half = x0, hi half = x1
    uint32_t r;
    asm("cvt.rn.satfinite.bf16x2.f32 %0, %1, %2;" : "=r"(r) : "f"(x1), "f"(x0));
    return r;
}
DEVFN float bf16rt(float x) { return __bfloat162float(__float2bfloat16_rn(x)); }

DEVFN void ldsm4(uint32_t& r0, uint32_t& r1, uint32_t& r2, uint32_t& r3,
                 uint32_t addr) {
    asm volatile("ldmatrix.sync.aligned.m8n8.x4.shared.b16 {%0,%1,%2,%3}, [%4];"
                 : "=r"(r0), "=r"(r1), "=r"(r2), "=r"(r3) : "r"(addr));
}
DEVFN void ldsm4t(uint32_t& r0, uint32_t& r1, uint32_t& r2, uint32_t& r3,
                  uint32_t addr) {
    asm volatile("ldmatrix.sync.aligned.m8n8.x4.trans.shared.b16 {%0,%1,%2,%3}, [%4];"
                 : "=r"(r0), "=r"(r1), "=r"(r2), "=r"(r3) : "r"(addr));
}
DEVFN void mma16816(float* d, const uint32_t* a, uint32_t b0, uint32_t b1) {
    asm volatile(
        "mma.sync.aligned.m16n8k16.row.col.f32.bf16.bf16.f32 "
        "{%0,%1,%2,%3}, {%4,%5,%6,%7}, {%8,%9}, {%0,%1,%2,%3};"
        : "+f"(d[0]), "+f"(d[1]), "+f"(d[2]), "+f"(d[3])
        : "r"(a[0]), "r"(a[1]), "r"(a[2]), "r"(a[3]), "r"(b0), "r"(b1));
}
DEVFN void cpasync16(uint32_t dst, const void* src) {
    asm volatile("cp.async.cg.shared.global [%0], [%1], 16;"
                 :: "r"(dst), "l"(src));
}
#define CP_COMMIT() asm volatile("cp.async.commit_group;" ::: "memory")
#define CP_WAIT0() asm volatile("cp.async.wait_group 0;" ::: "memory")

// ===========================================================================
// Scratch
// ===========================================================================
__device__ float g_q[786432];
__device__ float g_o[786432];
__device__ float g_opart[1572864];     // [2][8192][96] unnormalized O
__device__ float g_ml[32768];          // [2][8192][2] (m, l)
// Padded bf16 hi/lo tile images: [64 tiles][hi|lo][128 rows][104 ch] halves
__device__ uint32_t g_kpad[851968];    // 64 * 13312 u32
__device__ uint32_t g_vpad[851968];

#define PITCH 104                       /* halves per image row (208 B)        */
#define TILE_U32 13312                  /* u32 per (hi+lo) tile image          */
#define HALF_OFF_B 26624                /* byte offset hi -> lo block          */
#define KBUF_B 53248                    /* one tile image in smem              */
#define ATTN_SMEM_B (3 * KBUF_B)        /* K ping + K pong + V = 159744 B      */

// ===========================================================================
// Fused QKV conv, BN=64 for occupancy: grid (64, 2, 3).
// z=0 -> Q (fp32), z=1 -> K image, z=2 -> V image (bf16 hi/lo, prep fused).
// ===========================================================================
__global__ __launch_bounds__(256) void qkv_conv_kernel(
    const float* __restrict__ x,
    const float* __restrict__ w1, const float* __restrict__ b1,
    const float* __restrict__ w2, const float* __restrict__ b2,
    const float* __restrict__ w3, const float* __restrict__ b3) {
    __shared__ float AsT[16][98];
    __shared__ float Bs[16][64];
    const int tid = threadIdx.x;
    const int tx = tid & 15;
    const int ty = tid >> 4;
    const int b = blockIdx.y;
    const int z = blockIdx.z;
    const int n0 = blockIdx.x * 64;
    const float* A = (z == 0) ? w1 : (z == 1) ? w2 : w3;
    const float* bias = (z == 0) ? b1 : (z == 1) ? b2 : b3;
    const float* Bb = x + (size_t)b * 192 * 4096 + n0;
    const int r0 = ty * 6;
    const int c0 = tx * 4;

    unsigned long long acc[6][2];
#pragma unroll
    for (int r = 0; r < 6; ++r) { acc[r][0] = 0ULL; acc[r][1] = 0ULL; }

    for (int kc = 0; kc < 192; kc += 16) {
        __syncthreads();
        for (int i = tid; i < 96 * 16; i += 256) {
            int k = i & 15, r = i >> 4;
            AsT[k][r] = A[r * 192 + kc + k];
        }
        for (int i = tid; i < 16 * 64; i += 256) {
            int n = i & 63, k = i >> 6;
            Bs[k][n] = Bb[(size_t)(kc + k) * 4096 + n];
        }
        __syncthreads();
#pragma unroll
        for (int k = 0; k < 16; ++k) {
            float2 a01 = *(const float2*)&AsT[k][r0];
            float2 a23 = *(const float2*)&AsT[k][r0 + 2];
            float2 a45 = *(const float2*)&AsT[k][r0 + 4];
            ulonglong2 bv = *(const ulonglong2*)&Bs[k][c0];
            float av[6] = {a01.x, a01.y, a23.x, a23.y, a45.x, a45.y};
#pragma unroll
            for (int r = 0; r < 6; ++r) {
                unsigned long long ap = pack2(av[r], av[r]);
                acc[r][0] = fma2(ap, bv.x, acc[r][0]);
                acc[r][1] = fma2(ap, bv.y, acc[r][1]);
            }
        }
    }

    uint32_t* img = (z == 1) ? g_kpad : g_vpad;
#pragma unroll
    for (int r = 0; r < 6; ++r) {
        int m = r0 + r;
        float bv = bias[m];
        int f = b * 393216 + m * 4096 + n0 + c0;
        float2 t0 = unpk2(acc[r][0]);
        float2 t1 = unpk2(acc[r][1]);
        float o[4] = {t0.x + bv, t0.y + bv, t1.x + bv, t1.y + bv};
        if (z == 0) {
            *(float4*)&g_q[f] = make_float4(o[0], o[1], o[2], o[3]);
        } else {
#pragma unroll
            for (int j = 0; j < 2; ++j) {
                int f2 = f + 2 * j;
                int row = f2 / 96;
                int ch = f2 - row * 96;
                uint32_t* d = img + (row >> 7) * TILE_U32 + (row & 127) * 52 +
                              (ch >> 1);
                float x0 = o[2 * j], x1 = o[2 * j + 1];
                d[0] = packbf(x0, x1);
                d[6656] = packbf(x0 - bf16rt(x0), x1 - bf16rt(x1));
            }
        }
    }
}

// ===========================================================================
// Final conv1x1 + bias + residual, BN=64: grid (64, 2, 2)
// ===========================================================================
__global__ __launch_bounds__(256) void final_conv_kernel(
    const float* __restrict__ A, const float* __restrict__ bias,
    const float* __restrict__ B, const float* __restrict__ R,
    float* __restrict__ C) {
    __shared__ float AsT[16][98];
    __shared__ float Bs[16][64];
    const int tid = threadIdx.x;
    const int tx = tid & 15;
    const int ty = tid >> 4;
    const int mo = blockIdx.z * 96;
    const int b = blockIdx.y;
    const int n0 = blockIdx.x * 64;
    const float* Ab = A + (size_t)mo * 96;
    const float* Bb = B + (size_t)b * 96 * 4096 + n0;
    const int r0 = ty * 6;
    const int c0 = tx * 4;

    unsigned long long acc[6][2];
#pragma unroll
    for (int r = 0; r < 6; ++r) { acc[r][0] = 0ULL; acc[r][1] = 0ULL; }

    for (int kc = 0; kc < 96; kc += 16) {
        __syncthreads();
        for (int i = tid; i < 96 * 16; i += 256) {
            int k = i & 15, r = i >> 4;
            AsT[k][r] = Ab[r * 96 + kc + k];
        }
        for (int i = tid; i < 16 * 64; i += 256) {
            int n = i & 63, k = i >> 6;
            Bs[k][n] = Bb[(size_t)(kc + k) * 4096 + n];
        }
        __syncthreads();
#pragma unroll
        for (int k = 0; k < 16; ++k) {
            float2 a01 = *(const float2*)&AsT[k][r0];
            float2 a23 = *(const float2*)&AsT[k][r0 + 2];
            float2 a45 = *(const float2*)&AsT[k][r0 + 4];
            ulonglong2 bv = *(const ulonglong2*)&Bs[k][c0];
            float av[6] = {a01.x, a01.y, a23.x, a23.y, a45.x, a45.y};
#pragma unroll
            for (int r = 0; r < 6; ++r) {
                unsigned long long ap = pack2(av[r], av[r]);
                acc[r][0] = fma2(ap, bv.x, acc[r][0]);
                acc[r][1] = fma2(ap, bv.y, acc[r][1]);
            }
        }
    }
#pragma unroll
    for (int r = 0; r < 6; ++r) {
        int m = mo + r0 + r;
        float bv = bias[m];
        size_t base = ((size_t)b * 192 + m) * 4096 + n0 + c0;
        float2 t0 = unpk2(acc[r][0]);
        float2 t1 = unpk2(acc[r][1]);
        float4 rv = *(const float4*)&R[base];
        *(float4*)&C[base] = make_float4(t0.x + bv + rv.x, t0.y + bv + rv.y,
                                         t1.x + bv + rv.z, t1.y + bv + rv.w);
    }
}

// ===========================================================================
// mma.sync flash attention with cp.async pipelining and paired-p MMA
// interleave (4 independent accumulator chains per group).
// grid = 128 (qblk*2 + khalf), 256 threads, 8 warps, 16 q-rows/warp.
// ===========================================================================
__global__ __launch_bounds__(256, 1) void attn_mma_kernel() {
    extern __shared__ __align__(16) char smraw[];
    const int tid = threadIdx.x;
    const int lane = tid & 31;
    const int w = tid >> 5;
    const int qblk = blockIdx.x >> 1;
    const int khalf = blockIdx.x & 1;

    const int rquad = lane >> 2;
    const int c2 = 2 * (lane & 3);
    const int rowg0 = qblk * 128 + w * 16 + rquad;
    const int rowg1 = rowg0 + 8;

    const uint32_t sbase = smem_u32(smraw);
    const int g = lane >> 3, j8 = lane & 7;
    const uint32_t k_lane =
        2u * (uint32_t)((j8 + ((g >> 1) & 1) * 8) * PITCH + (g & 1) * 8);
    const uint32_t v_lane =
        2u * (uint32_t)((j8 + (g & 1) * 8) * PITCH + ((g >> 1) & 1) * 8);
    const uint32_t kbase0 = sbase;
    const uint32_t kbase1 = sbase + KBUF_B;
    const uint32_t vbase = sbase + 2 * KBUF_B;

    // ---- Q fragments (hi/lo), resident ----
    uint32_t Qh[6][4], Ql[6][4];
#pragma unroll
    for (int s = 0; s < 6; ++s) {
        const float* q0 = &g_q[(size_t)rowg0 * 96 + s * 16 + c2];
        const float* q1 = &g_q[(size_t)rowg1 * 96 + s * 16 + c2];
        float2 x0 = *(const float2*)q0;
        float2 x1 = *(const float2*)q1;
        float2 x2 = *(const float2*)(q0 + 8);
        float2 x3 = *(const float2*)(q1 + 8);
        Qh[s][0] = packbf(x0.x, x0.y);
        Qh[s][1] = packbf(x1.x, x1.y);
        Qh[s][2] = packbf(x2.x, x2.y);
        Qh[s][3] = packbf(x3.x, x3.y);
        Ql[s][0] = packbf(x0.x - bf16rt(x0.x), x0.y - bf16rt(x0.y));
        Ql[s][1] = packbf(x1.x - bf16rt(x1.x), x1.y - bf16rt(x1.y));
        Ql[s][2] = packbf(x2.x - bf16rt(x2.x), x2.y - bf16rt(x2.y));
        Ql[s][3] = packbf(x3.x - bf16rt(x3.x), x3.y - bf16rt(x3.y));
    }

    float m0 = __int_as_float(0xff800000), m1 = m0;
    float l0 = 0.0f, l1 = 0.0f;
    float accO[12][4];
#pragma unroll
    for (int n = 0; n < 12; ++n)
#pragma unroll
        for (int j = 0; j < 4; ++j) accO[n][j] = 0.0f;

    // ---- prologue: async-copy K tile 0 ----
    {
        const uint4* ks = (const uint4*)g_kpad + (size_t)(khalf * 32) * 3328;
#pragma unroll
        for (int i = 0; i < 13; ++i)
            cpasync16(kbase0 + 16u * (tid + 256 * i), ks + tid + 256 * i);
        CP_COMMIT();
    }

    for (int it = 0; it < 32; ++it) {
        const int tile = khalf * 32 + it;
        const uint32_t kcur = (it & 1) ? kbase1 : kbase0;

        CP_WAIT0();
        __syncthreads();

        // ---- kick V_it copy (overlaps S-phase) ----
        {
            const uint4* vs = (const uint4*)g_vpad + (size_t)tile * 3328;
#pragma unroll
            for (int i = 0; i < 13; ++i)
                cpasync16(vbase + 16u * (tid + 256 * i), vs + tid + 256 * i);
            CP_COMMIT();
        }

        // ---- S = Q K^T : p-pairs -> 4 independent chains ----
        float accS[16][4];
#pragma unroll
        for (int t = 0; t < 16; ++t)
#pragma unroll
            for (int j = 0; j < 4; ++j) accS[t][j] = 0.0f;
#pragma unroll
        for (int p2 = 0; p2 < 8; p2 += 2) {
#pragma unroll
            for (int s = 0; s < 6; ++s) {
                uint32_t ka = kcur + k_lane +
                              2u * (uint32_t)(p2 * 16 * PITCH + s * 16);
                uint32_t kb = ka + 2u * (uint32_t)(16 * PITCH);
                uint32_t h0, h1, h2, h3, e0, e1, e2, e3;
                uint32_t i0, i1, i2, i3, f0, f1, f2, f3;
                ldsm4(h0, h1, h2, h3, ka);
                ldsm4(i0, i1, i2, i3, kb);
                ldsm4(e0, e1, e2, e3, ka + HALF_OFF_B);
                ldsm4(f0, f1, f2, f3, kb + HALF_OFF_B);
                mma16816(accS[2 * p2], Qh[s], h0, h1);
                mma16816(accS[2 * p2 + 1], Qh[s], h2, h3);
                mma16816(accS[2 * p2 + 2], Qh[s], i0, i1);
                mma16816(accS[2 * p2 + 3], Qh[s], i2, i3);
                mma16816(accS[2 * p2], Qh[s], e0, e1);
                mma16816(accS[2 * p2 + 1], Qh[s], e2, e3);
                mma16816(accS[2 * p2 + 2], Qh[s], f0, f1);
                mma16816(accS[2 * p2 + 3], Qh[s], f2, f3);
                mma16816(accS[2 * p2], Ql[s], h0, h1);
                mma16816(accS[2 * p2 + 1], Ql[s], h2, h3);
                mma16816(accS[2 * p2 + 2], Ql[s], i0, i1);
                mma16816(accS[2 * p2 + 3], Ql[s], i2, i3);
            }
        }

        CP_WAIT0();
        __syncthreads();

        // ---- kick K_{it+1} copy (overlaps softmax + PV-phase) ----
        if (it < 31) {
            const uint4* ks = (const uint4*)g_kpad + (size_t)(tile + 1) * 3328;
            const uint32_t knext = (it & 1) ? kbase0 : kbase1;
#pragma unroll
            for (int i = 0; i < 13; ++i)
                cpasync16(knext + 16u * (tid + 256 * i), ks + tid + 256 * i);
            CP_COMMIT();
        }

        // ---- online softmax ----
        float mx0 = __int_as_float(0xff800000), mx1 = mx0;
#pragma unroll
        for (int t = 0; t < 16; ++t) {
            mx0 = fmaxf(mx0, fmaxf(accS[t][0], accS[t][1]));
            mx1 = fmaxf(mx1, fmaxf(accS[t][2], accS[t][3]));
        }
        mx0 = fmaxf(mx0, __shfl_xor_sync(0xffffffffu, mx0, 1));
        mx0 = fmaxf(mx0, __shfl_xor_sync(0xffffffffu, mx0, 2));
        mx1 = fmaxf(mx1, __shfl_xor_sync(0xffffffffu, mx1, 1));
        mx1 = fmaxf(mx1, __shfl_xor_sync(0xffffffffu, mx1, 2));
        float mn0 = fmaxf(m0, mx0), mn1 = fmaxf(m1, mx1);
        float al0 = __expf(m0 - mn0), al1 = __expf(m1 - mn1);

        uint32_t Ph[8][4], Pl[8][4];
        float sum0 = 0.0f, sum1 = 0.0f;
#pragma unroll
        for (int t = 0; t < 16; ++t) {
            float p0 = __expf(accS[t][0] - mn0);
            float p1 = __expf(accS[t][1] - mn0);
            float p2 = __expf(accS[t][2] - mn1);
            float p3 = __expf(accS[t][3] - mn1);
            sum0 += p0 + p1;
            sum1 += p2 + p3;
            int j = t >> 1;
            int rr = (t & 1) * 2;
            Ph[j][rr] = packbf(p0, p1);
            Ph[j][rr + 1] = packbf(p2, p3);
            Pl[j][rr] = packbf(p0 - bf16rt(p0), p1 - bf16rt(p1));
            Pl[j][rr + 1] = packbf(p2 - bf16rt(p2), p3 - bf16rt(p3));
        }
        sum0 += __shfl_xor_sync(0xffffffffu, sum0, 1);
        sum0 += __shfl_xor_sync(0xffffffffu, sum0, 2);
        sum1 += __shfl_xor_sync(0xffffffffu, sum1, 1);
        sum1 += __shfl_xor_sync(0xffffffffu, sum1, 2);
        l0 = l0 * al0 + sum0;
        l1 = l1 * al1 + sum1;
        m0 = mn0;
        m1 = mn1;

        // ---- O = al*O + P V : p-pairs -> 4 independent chains ----
#pragma unroll
        for (int n = 0; n < 12; ++n) {
            accO[n][0] *= al0;
            accO[n][1] *= al0;
            accO[n][2] *= al1;
            accO[n][3] *= al1;
        }
#pragma unroll
        for (int s = 0; s < 8; ++s) {
#pragma unroll
            for (int p2 = 0; p2 < 6; p2 += 2) {
                uint32_t va = vbase + v_lane +
                              2u * (uint32_t)(s * 16 * PITCH + p2 * 16);
                uint32_t vb = va + 32u;
                uint32_t h0, h1, h2, h3, e0, e1, e2, e3;
                uint32_t i0, i1, i2, i3, f0, f1, f2, f3;
                ldsm4t(h0, h1, h2, h3, va);
                ldsm4t(i0, i1, i2, i3, vb);
                ldsm4t(e0, e1, e2, e3, va + HALF_OFF_B);
                ldsm4t(f0, f1, f2, f3, vb + HALF_OFF_B);
                mma16816(accO[2 * p2], Ph[s], h0, h1);
                mma16816(accO[2 * p2 + 1], Ph[s], h2, h3);
                mma16816(accO[2 * p2 + 2], Ph[s], i0, i1);
                mma16816(accO[2 * p2 + 3], Ph[s], i2, i3);
                mma16816(accO[2 * p2], Ph[s], e0, e1);
                mma16816(accO[2 * p2 + 1], Ph[s], e2, e3);
                mma16816(accO[2 * p2 + 2], Ph[s], f0, f1);
                mma16816(accO[2 * p2 + 3], Ph[s], f2, f3);
                mma16816(accO[2 * p2], Pl[s], h0, h1);
                mma16816(accO[2 * p2 + 1], Pl[s], h2, h3);
                mma16816(accO[2 * p2 + 2], Pl[s], i0, i1);
                mma16816(accO[2 * p2 + 3], Pl[s], i2, i3);
            }
        }
    }

    // ---- write partials ----
    float* op = g_opart + (size_t)khalf * 786432;
#pragma unroll
    for (int n = 0; n < 12; ++n) {
        int col = n * 8 + c2;
        *(float2*)&op[(size_t)rowg0 * 96 + col] = make_float2(accO[n][0], accO[n][1]);
        *(float2*)&op[(size_t)rowg1 * 96 + col] = make_float2(accO[n][2], accO[n][3]);
    }
    if ((lane & 3) == 0) {
        ((float2*)g_ml)[(size_t)khalf * 8192 + rowg0] = make_float2(m0, l0);
        ((float2*)g_ml)[(size_t)khalf * 8192 + rowg1] = make_float2(m1, l1);
    }
}

// ===========================================================================
// Combine the two key-half partials
// ===========================================================================
__global__ __launch_bounds__(768) void combine_kernel() {
    int e = blockIdx.x * 768 + threadIdx.x;
    int r = e / 96;
    float2 ml0 = ((const float2*)g_ml)[r];
    float2 ml1 = ((const float2*)g_ml)[8192 + r];
    float M = fmaxf(ml0.x, ml1.x);
    float w0 = __expf(ml0.x - M);
    float w1 = __expf(ml1.x - M);
    float inv = 1.0f / (w0 * ml0.y + w1 * ml1.y);
    g_o[e] = (w0 * g_opart[e] + w1 * g_opart[786432 + e]) * inv;
}

// ===========================================================================
// Launch
// ===========================================================================
extern "C" void kernel_launch(void* const* d_in, const int* in_sizes, int n_in,
                              void* d_out, int out_size) {
    (void)in_sizes; (void)n_in; (void)out_size;
    const float* x = (const float*)d_in[0];
    const float* w1 = (const float*)d_in[1];
    const float* b1 = (const float*)d_in[2];
    const float* w2 = (const float*)d_in[3];
    const float* b2 = (const float*)d_in[4];
    const float* w3 = (const float*)d_in[5];
    const float* b3 = (const float*)d_in[6];
    const float* wl = (const float*)d_in[7];
    const float* bl = (const float*)d_in[8];
    float* out = (float*)d_out;

    void* op;
    cudaGetSymbolAddress(&op, g_o);

    cudaFuncSetAttribute(attn_mma_kernel,
                         cudaFuncAttributeMaxDynamicSharedMemorySize, ATTN_SMEM_B);

    qkv_conv_kernel<<<dim3(64, 2, 3), 256>>>(x, w1, b1, w2, b2, w3, b3);

    attn_mma_kernel<<<128, 256, ATTN_SMEM_B>>>();

    combine_kernel<<<1024, 768>>>();

    final_conv_kernel<<<dim3(64, 2, 2), 256>>>(wl, bl, (const float*)op, x, out);
}